// round 4
// baseline (speedup 1.0000x reference)
#include <cuda_runtime.h>
#include <math.h>
#include <stdint.h>

#define BB     32
#define NN     8732
#define NCLS   20
#define DCOL   33
#define NMSMAX 100
#define TOPK   200
#define CONF_T 0.01f
#define IOU_T  0.45f
#define TILE   128
#define NTILES 69            // ceil(8732/128)
#define NBC    (BB * NCLS)   // 640
#define CAP    384
#define MAXW   12            // ceil(CAP/32)

// ---------------- scratch ----------------
__device__ float4             g_boxes   [(size_t)BB * NN];
__device__ int                g_candcnt [NBC];
__device__ unsigned long long g_cand    [NBC * CAP];
__device__ int                g_val     [NBC * NMSMAX];
__device__ float              g_selscore[NBC * NMSMAX];
__device__ float4             g_selbox  [NBC * NMSMAX];

// monotonic float <-> u32 order-preserving map
__device__ __forceinline__ unsigned fmap(float f) {
    unsigned u = __float_as_uint(f);
    return (u & 0x80000000u) ? ~u : (u | 0x80000000u);
}
__device__ __forceinline__ float funmap(unsigned u) {
    return __uint_as_float((u & 0x80000000u) ? (u & 0x7FFFFFFFu) : ~u);
}

// ---------------- phase 0: zero candidate counters ----------------
__global__ void init_kernel() { g_candcnt[threadIdx.x] = 0; }

// ---------------- phase 1: decode + candidate filter ----------------
__global__ void __launch_bounds__(256) decode_kernel(const float* __restrict__ y)
{
    __shared__ float sh[TILE * DCOL];
    int blk = blockIdx.x;
    int b   = blk / NTILES;
    int t   = blk % NTILES;
    int n0  = t * TILE;
    int count = min(TILE, NN - n0);

    const float* src = y + ((size_t)b * NN + n0) * DCOL;
    for (int i = threadIdx.x; i < count * DCOL; i += 256) sh[i] = src[i];
    __syncthreads();

    const unsigned LO = fmap(0.975f);
    for (int k = threadIdx.x; k < NCLS * count; k += 256) {
        int c  = k / count;
        int nn = k - c * count;
        float s = sh[nn * DCOL + 1 + c];
        if (s > CONF_T) {
            unsigned m = fmap(s);
            if (m >= LO) {
                int bc = b * NCLS + c;
                int p = atomicAdd(&g_candcnt[bc], 1);
                if (p < CAP)
                    g_cand[bc * CAP + p] = ((unsigned long long)m << 32) |
                                           (unsigned)(0xFFFFFFFFu - (unsigned)(n0 + nn));
            }
        }
    }
    if (threadIdx.x < count) {
        const float* r = sh + threadIdx.x * DCOL;
        float cx_p = r[21], cy_p = r[22], w_p = r[23], h_p = r[24];
        float xa1  = r[25], ya1  = r[26], xa2 = r[27], ya2 = r[28];
        float vcx  = r[29], vcy  = r[30], vw  = r[31], vh  = r[32];
        float w_a = xa2 - xa1, h_a = ya2 - ya1;
        float cx_a = (xa2 + xa1) * 0.5f, cy_a = (ya2 + ya1) * 0.5f;
        float cx = cx_p * vcx * w_a + cx_a;
        float cy = cy_p * vcy * h_a + cy_a;
        float w  = expf(w_p * vw) * w_a;
        float h  = expf(h_p * vh) * h_a;
        float4 o;
        o.x = (cx - 0.5f * w) * 512.0f;
        o.y = (cy - 0.5f * h) * 512.0f;
        o.z = (cx + 0.5f * w) * 512.0f;
        o.w = (cy + 0.5f * h) * 512.0f;
        g_boxes[(size_t)b * NN + n0 + threadIdx.x] = o;
    }
}

// ---------------- phase 2: bitmask greedy NMS, one CTA per (b,c) -----------
__global__ void __launch_bounds__(256) nms_kernel(const float* __restrict__ y)
{
    const int bc = blockIdx.x;
    const int b  = bc / NCLS;
    const int c  = bc - b * NCLS;
    const float4* bx = g_boxes + (size_t)b * NN;

    __shared__ unsigned long long cand[512];           // 4 KB (pow2 pad)
    __shared__ float4  cbox [CAP];                     // 6 KB
    __shared__ float   carea[CAP];                     // 1.5 KB
    __shared__ unsigned mask[CAP * MAXW];              // 18 KB
    __shared__ float4  kbox [NMSMAX];                  // kept across windows
    __shared__ float   karea[NMSMAX];
    __shared__ unsigned presup[MAXW];
    __shared__ int s_cnt, s_ns;

    const int tid  = threadIdx.x;
    const int lane = tid & 31;
    const unsigned LO = fmap(0.975f);
    if (tid == 0) s_ns = 0;

    int cnt0 = g_candcnt[bc];
    bool listFirst = (cnt0 <= CAP);
    unsigned hiW = listFirst ? LO : 0xFFFFFFFFu;   // unscanned region is [CONF, hiW)
    __syncthreads();

    for (;;) {
        int cnt;
        unsigned windowLo;
        if (listFirst) {
            listFirst = false;
            cnt = cnt0;
            for (int i = tid; i < cnt; i += 256) cand[i] = g_cand[bc * CAP + i];
            windowLo = hiW;        // remaining region after this window: [0, LO)
            __syncthreads();
        } else {
            // exact fallback: gather from raw y in [loW, hiW), halving on overflow
            unsigned loW = 0;
            for (;;) {
                __syncthreads();
                if (tid == 0) s_cnt = 0;
                __syncthreads();
                for (int i = tid; i < NN; i += 256) {
                    float val = y[((size_t)b * NN + i) * DCOL + 1 + c];
                    if (val > CONF_T) {
                        unsigned m = fmap(val);
                        if (m >= loW && m < hiW) {
                            int p = atomicAdd(&s_cnt, 1);
                            if (p < CAP)
                                cand[p] = ((unsigned long long)m << 32) |
                                          (unsigned)(0xFFFFFFFFu - (unsigned)i);
                        }
                    }
                }
                __syncthreads();
                cnt = s_cnt;
                if (cnt <= CAP || hiW - loW <= 1) break;
                loW = loW + ((hiW - loW) >> 1);
            }
            if (cnt > CAP) cnt = CAP;
            windowLo = loW;
        }

        if (cnt > 0) {
            // ---- bitonic sort descending ----
            int P = 32; while (P < cnt) P <<= 1;
            for (int i = cnt + tid; i < P; i += 256) cand[i] = 0ull;
            __syncthreads();
            for (int ks = 2; ks <= P; ks <<= 1) {
                for (int j = ks >> 1; j > 0; j >>= 1) {
                    for (int i = tid; i < P; i += 256) {
                        int ixj = i ^ j;
                        if (ixj > i) {
                            unsigned long long a = cand[i], q = cand[ixj];
                            bool desc = ((i & ks) == 0);
                            if (desc ? (a < q) : (a > q)) { cand[i] = q; cand[ixj] = a; }
                        }
                    }
                    __syncthreads();
                }
            }

            // ---- boxes + areas (sorted order) ----
            for (int t = tid; t < cnt; t += 256) {
                int idx = (int)(0xFFFFFFFFu - (unsigned)(cand[t] & 0xFFFFFFFFull));
                float4 Bt = __ldg(&bx[idx]);
                cbox[t]  = Bt;
                carea[t] = fmaxf(Bt.z - Bt.x, 0.0f) * fmaxf(Bt.w - Bt.y, 0.0f);
            }
            __syncthreads();

            // ---- pre-suppression vs kept boxes from earlier windows ----
            int nsPrev = s_ns;
            int P32 = (cnt + 31) & ~31;
            for (int t = tid; t < P32; t += 256) {
                bool sup = false;
                if (t < cnt) {
                    float4 Bt = cbox[t];
                    float at = carea[t];
                    for (int j = 0; j < nsPrev; ++j) {
                        float4 Kj = kbox[j];
                        float ix1 = fmaxf(Kj.x, Bt.x), iy1 = fmaxf(Kj.y, Bt.y);
                        float ix2 = fminf(Kj.z, Bt.z), iy2 = fminf(Kj.w, Bt.w);
                        float inter = fmaxf(ix2 - ix1, 0.0f) * fmaxf(iy2 - iy1, 0.0f);
                        float iou = inter / (karea[j] + at - inter + 1e-9f);
                        sup |= (iou > IOU_T);
                    }
                }
                unsigned wmask = __ballot_sync(0xFFFFFFFFu, sup);
                if (lane == 0) presup[t >> 5] = wmask;
            }

            // ---- suppression bit-matrix (row t suppresses u > t) ----
            int W = (cnt + 31) >> 5;
            for (int t = tid; t < cnt; t += 256) {
                float4 Bt = cbox[t];
                float  at = carea[t];
                int wlo = (t + 1) >> 5;
                for (int w = wlo; w < W; ++w) {
                    unsigned word = 0;
                    int ub = w << 5;
                    int us = (ub > t + 1) ? ub : t + 1;
                    int ue = min(ub + 32, cnt);
                    for (int u = us; u < ue; ++u) {
                        float4 Bu = cbox[u];
                        float ix1 = fmaxf(Bt.x, Bu.x), iy1 = fmaxf(Bt.y, Bu.y);
                        float ix2 = fminf(Bt.z, Bu.z), iy2 = fminf(Bt.w, Bu.w);
                        float inter = fmaxf(ix2 - ix1, 0.0f) * fmaxf(iy2 - iy1, 0.0f);
                        float iou = inter / (at + carea[u] - inter + 1e-9f);
                        if (iou > IOU_T) word |= 1u << (u - ub);
                    }
                    mask[t * MAXW + w] = word;
                }
            }
            __syncthreads();

            // ---- single-thread bitmask greedy scan ----
            if (tid == 0) {
                int ns = s_ns;
                unsigned cur = 0;
                for (int t = 0; t < cnt && ns < NMSMAX; ++t) {
                    if ((t & 31) == 0) cur = presup[t >> 5];
                    if (!((cur >> (t & 31)) & 1u)) {
                        unsigned long long key = cand[t];
                        float4 Bt = cbox[t];
                        int o = bc * NMSMAX + ns;
                        g_val[o]      = 1;
                        g_selscore[o] = funmap((unsigned)(key >> 32));
                        g_selbox[o]   = Bt;
                        kbox[ns]  = Bt;
                        karea[ns] = carea[t];
                        ++ns;
                        int wlo = (t + 1) >> 5;
                        int tw  = t >> 5;
                        #pragma unroll
                        for (int w = 0; w < MAXW; ++w) {
                            if (w >= wlo && w < W) {
                                unsigned rw = mask[t * MAXW + w];
                                if (w == tw) cur |= rw;
                                presup[w] |= rw;
                            }
                        }
                    }
                }
                s_ns = ns;
            }
            __syncthreads();
        }

        if (s_ns >= NMSMAX) break;
        hiW = windowLo;
        if (hiW == 0) break;
    }
    __syncthreads();

    int nsf = s_ns;
    for (int j = nsf + tid; j < NMSMAX; j += 256) {
        int o = bc * NMSMAX + j;
        g_val[o]      = 0;
        g_selscore[o] = -INFINITY;
    }
}

// ---------------- phase 3: rank-based top-200 ------------------------------
// Per-class lists are already key-descending, so rank = in-class position +
// sum of binary-search counts over the other 19 sorted lists.
__global__ void __launch_bounds__(1024) topk_kernel(float* __restrict__ out)
{
    const int b   = blockIdx.x;
    const int tid = threadIdx.x;
    __shared__ unsigned long long keys[NCLS * NMSMAX];   // 2000

    for (int k = tid; k < NCLS * NMSMAX; k += 1024) {
        float s = g_selscore[b * NCLS * NMSMAX + k];
        keys[k] = ((unsigned long long)fmap(s) << 32) |
                  (unsigned)(0xFFFFFFFFu - (unsigned)k);
    }
    __syncthreads();

    for (int k = tid; k < NCLS * NMSMAX; k += 1024) {
        unsigned long long my = keys[k];
        int c0 = k / NMSMAX;
        int rank = k - c0 * NMSMAX;            // in-class position (list is desc)
        #pragma unroll 4
        for (int cc = 0; cc < NCLS; ++cc) {
            if (cc == c0) continue;
            const unsigned long long* L = keys + cc * NMSMAX;
            int lo = 0, hi = NMSMAX;
            while (lo < hi) {
                int mid = (lo + hi) >> 1;
                if (L[mid] > my) lo = mid + 1; else hi = mid;
            }
            rank += lo;
        }
        if (rank < TOPK) {
            int base = b * NCLS * NMSMAX + k;
            float* o = out + ((size_t)b * TOPK + rank) * 6;
            if (g_val[base]) {
                float4 box = g_selbox[base];
                o[0] = (float)c0 + 1.0f;
                o[1] = g_selscore[base];
                o[2] = box.x; o[3] = box.y; o[4] = box.z; o[5] = box.w;
            } else {
                o[0] = 1.0f; o[1] = 0.0f;
                o[2] = 0.0f; o[3] = 0.0f; o[4] = 0.0f; o[5] = 0.0f;
            }
        }
    }
}

// -----------------------------------------------------------------------------
extern "C" void kernel_launch(void* const* d_in, const int* in_sizes, int n_in,
                              void* d_out, int out_size)
{
    const float* y = (const float*)d_in[0];
    float* out = (float*)d_out;
    init_kernel<<<1, NBC>>>();
    decode_kernel<<<BB * NTILES, 256>>>(y);
    nms_kernel<<<NBC, 256>>>(y);
    topk_kernel<<<BB, 1024>>>(out);
}

// round 5
// speedup vs baseline: 1.0568x; 1.0568x over previous
#include <cuda_runtime.h>
#include <math.h>
#include <stdint.h>

#define BB     32
#define NN     8732
#define NCLS   20
#define DCOL   33
#define NMSMAX 100
#define TOPK   200
#define CONF_T 0.01f
#define IOU_T  0.45f
#define TILE   128
#define NTILES 69            // ceil(8732/128)
#define NBC    (BB * NCLS)   // 640
#define CAP    384
#define MAXW   12            // ceil(CAP/32)
#define STAGE  64            // per-class staging slots per tile

// ---------------- scratch ----------------
__device__ float4             g_boxes   [(size_t)BB * NN];
__device__ int                g_candcnt [NBC];           // static-zero initially; topk resets
__device__ unsigned long long g_cand    [NBC * CAP];
__device__ float              g_selscore[NBC * NMSMAX];
__device__ float4             g_selbox  [NBC * NMSMAX];

// monotonic float <-> u32 order-preserving map
__device__ __forceinline__ unsigned fmap(float f) {
    unsigned u = __float_as_uint(f);
    return (u & 0x80000000u) ? ~u : (u | 0x80000000u);
}
__device__ __forceinline__ float funmap(unsigned u) {
    return __uint_as_float((u & 0x80000000u) ? (u & 0x7FFFFFFFu) : ~u);
}
#define FM_NEGINF 0x007FFFFFu   // fmap(-inf)

// decode one box from a 33-float row (same expression order as decode_kernel)
__device__ __forceinline__ float4 decode_box_row(const float* __restrict__ r)
{
    float cx_p = r[21], cy_p = r[22], w_p = r[23], h_p = r[24];
    float xa1  = r[25], ya1  = r[26], xa2 = r[27], ya2 = r[28];
    float vcx  = r[29], vcy  = r[30], vw  = r[31], vh  = r[32];
    float w_a = xa2 - xa1, h_a = ya2 - ya1;
    float cx_a = (xa2 + xa1) * 0.5f, cy_a = (ya2 + ya1) * 0.5f;
    float cx = cx_p * vcx * w_a + cx_a;
    float cy = cy_p * vcy * h_a + cy_a;
    float w  = expf(w_p * vw) * w_a;
    float h  = expf(h_p * vh) * h_a;
    float4 o;
    o.x = (cx - 0.5f * w) * 512.0f;
    o.y = (cy - 0.5f * h) * 512.0f;
    o.z = (cx + 0.5f * w) * 512.0f;
    o.w = (cy + 0.5f * h) * 512.0f;
    return o;
}

// ---------------- phase 1: decode + staged candidate filter ----------------
__global__ void __launch_bounds__(256) decode_kernel(const float* __restrict__ y)
{
    __shared__ float sh[TILE * DCOL];                          // 16.9 KB
    __shared__ unsigned long long s_skey[NCLS * STAGE];        // 10 KB
    __shared__ int s_scnt[NCLS];
    __shared__ int s_sbase[NCLS];
    __shared__ unsigned char s_bflag[TILE];

    const int tid = threadIdx.x;
    int blk = blockIdx.x;
    int b   = blk / NTILES;
    int t   = blk % NTILES;
    int n0  = t * TILE;
    int count = min(TILE, NN - n0);

    const float* src = y + ((size_t)b * NN + n0) * DCOL;
    for (int i = tid; i < count * DCOL; i += 256) sh[i] = src[i];
    if (tid < NCLS) s_scnt[tid] = 0;
    if (tid < TILE) s_bflag[tid] = 0;
    __syncthreads();

    const unsigned LO = fmap(0.975f);
    if (count == TILE) {
        for (int k = tid; k < NCLS * TILE; k += 256) {
            int c  = k >> 7;
            int nn = k & (TILE - 1);
            float s = sh[nn * DCOL + 1 + c];
            if (s > CONF_T) {
                unsigned m = fmap(s);
                if (m >= LO) {
                    s_bflag[nn] = 1;
                    unsigned long long key = ((unsigned long long)m << 32) |
                                             (unsigned)(0xFFFFFFFFu - (unsigned)(n0 + nn));
                    int p = atomicAdd(&s_scnt[c], 1);
                    if (p < STAGE) s_skey[c * STAGE + p] = key;
                    else {
                        int bc = b * NCLS + c;
                        int q = atomicAdd(&g_candcnt[bc], 1);
                        if (q < CAP) g_cand[bc * CAP + q] = key;
                    }
                }
            }
        }
    } else {
        for (int k = tid; k < NCLS * count; k += 256) {
            int c  = k / count;
            int nn = k - c * count;
            float s = sh[nn * DCOL + 1 + c];
            if (s > CONF_T) {
                unsigned m = fmap(s);
                if (m >= LO) {
                    s_bflag[nn] = 1;
                    unsigned long long key = ((unsigned long long)m << 32) |
                                             (unsigned)(0xFFFFFFFFu - (unsigned)(n0 + nn));
                    int p = atomicAdd(&s_scnt[c], 1);
                    if (p < STAGE) s_skey[c * STAGE + p] = key;
                    else {
                        int bc = b * NCLS + c;
                        int q = atomicAdd(&g_candcnt[bc], 1);
                        if (q < CAP) g_cand[bc * CAP + q] = key;
                    }
                }
            }
        }
    }
    __syncthreads();

    if (tid < NCLS) {
        int n = min(s_scnt[tid], STAGE);
        s_sbase[tid] = (n > 0) ? atomicAdd(&g_candcnt[b * NCLS + tid], n) : 0;
    }
    __syncthreads();
    for (int k = tid; k < NCLS * STAGE; k += 256) {
        int c = k >> 6;           // STAGE = 64
        int j = k & (STAGE - 1);
        int n = min(s_scnt[c], STAGE);
        if (j < n) {
            int q = s_sbase[c] + j;
            if (q < CAP) g_cand[(b * NCLS + c) * CAP + q] = s_skey[c * STAGE + j];
        }
    }

    // decode only candidate boxes
    if (tid < count && s_bflag[tid]) {
        g_boxes[(size_t)b * NN + n0 + tid] = decode_box_row(sh + tid * DCOL);
    }
}

// ---------------- phase 2: bitmask NMS with register-resident scan ----------
__global__ void __launch_bounds__(256) nms_kernel(const float* __restrict__ y)
{
    const int bc = blockIdx.x;
    const int b  = bc / NCLS;
    const int c  = bc - b * NCLS;
    const float4* bx = g_boxes + (size_t)b * NN;

    __shared__ unsigned long long cand[512];      // 4 KB
    __shared__ float4   cbox [CAP];               // 6 KB
    __shared__ float    carea[CAP];               // 1.5 KB
    __shared__ unsigned s_mask[CAP * MAXW];       // 18 KB
    __shared__ float4   kbox [NMSMAX];
    __shared__ float    karea[NMSMAX];
    __shared__ unsigned s_presup[MAXW];
    __shared__ int      s_keep[NMSMAX];
    __shared__ int      s_cnt, s_ns;

    const int tid  = threadIdx.x;
    const int lane = tid & 31;
    const unsigned LO = fmap(0.975f);
    if (tid == 0) s_ns = 0;

    int cnt0 = g_candcnt[bc];
    bool listFirst = (cnt0 <= CAP);
    unsigned hiW = listFirst ? LO : 0xFFFFFFFFu;   // region below this is unscanned
    __syncthreads();

    for (;;) {
        int cnt;
        unsigned windowLo;
        bool fromList = false;

        if (listFirst) {
            listFirst = false;
            fromList  = true;
            cnt = cnt0;
            for (int i = tid; i < cnt; i += 256) cand[i] = g_cand[bc * CAP + i];
            windowLo = hiW;                        // remaining region: [0, LO)
            __syncthreads();
        } else {
            // exact fallback: gather from raw y in [loW, hiW), halving on overflow
            unsigned loW = 0;
            for (;;) {
                __syncthreads();
                if (tid == 0) s_cnt = 0;
                __syncthreads();
                for (int i = tid; i < NN; i += 256) {
                    float val = y[((size_t)b * NN + i) * DCOL + 1 + c];
                    if (val > CONF_T) {
                        unsigned m = fmap(val);
                        if (m >= loW && m < hiW) {
                            int p = atomicAdd(&s_cnt, 1);
                            if (p < CAP)
                                cand[p] = ((unsigned long long)m << 32) |
                                          (unsigned)(0xFFFFFFFFu - (unsigned)i);
                        }
                    }
                }
                __syncthreads();
                cnt = s_cnt;
                if (cnt <= CAP || hiW - loW <= 1) break;
                loW = loW + ((hiW - loW) >> 1);
            }
            if (cnt > CAP) cnt = CAP;
            windowLo = loW;
        }

        if (cnt > 0) {
            // ---- bitonic sort descending ----
            int P = 32; while (P < cnt) P <<= 1;
            for (int i = cnt + tid; i < P; i += 256) cand[i] = 0ull;
            __syncthreads();
            for (int ks = 2; ks <= P; ks <<= 1) {
                for (int j = ks >> 1; j > 0; j >>= 1) {
                    for (int i = tid; i < P; i += 256) {
                        int ixj = i ^ j;
                        if (ixj > i) {
                            unsigned long long a = cand[i], q = cand[ixj];
                            bool desc = ((i & ks) == 0);
                            if (desc ? (a < q) : (a > q)) { cand[i] = q; cand[ixj] = a; }
                        }
                    }
                    __syncthreads();
                }
            }

            // ---- boxes + areas in sorted order ----
            if (fromList) {
                for (int t = tid; t < cnt; t += 256) {
                    int idx = (int)(0xFFFFFFFFu - (unsigned)(cand[t] & 0xFFFFFFFFull));
                    float4 Bt = __ldg(&bx[idx]);
                    cbox[t]  = Bt;
                    carea[t] = fmaxf(Bt.z - Bt.x, 0.0f) * fmaxf(Bt.w - Bt.y, 0.0f);
                }
            } else {
                for (int t = tid; t < cnt; t += 256) {
                    int idx = (int)(0xFFFFFFFFu - (unsigned)(cand[t] & 0xFFFFFFFFull));
                    const float* row = y + ((size_t)b * NN + idx) * DCOL;
                    float4 Bt = decode_box_row(row);
                    cbox[t]  = Bt;
                    carea[t] = fmaxf(Bt.z - Bt.x, 0.0f) * fmaxf(Bt.w - Bt.y, 0.0f);
                }
            }
            if (tid < MAXW) s_presup[tid] = 0;
            __syncthreads();

            // ---- pre-suppression vs kept boxes of earlier windows ----
            int nsPrev = s_ns;
            if (nsPrev > 0) {
                int P32 = (cnt + 31) & ~31;
                for (int t = tid; t < P32; t += 256) {
                    bool sup = false;
                    if (t < cnt) {
                        float4 Bt = cbox[t];
                        float at = carea[t];
                        for (int j = 0; j < nsPrev; ++j) {
                            float4 Kj = kbox[j];
                            float ix1 = fmaxf(Kj.x, Bt.x), iy1 = fmaxf(Kj.y, Bt.y);
                            float ix2 = fminf(Kj.z, Bt.z), iy2 = fminf(Kj.w, Bt.w);
                            float inter = fmaxf(ix2 - ix1, 0.0f) * fmaxf(iy2 - iy1, 0.0f);
                            float iou = inter / (karea[j] + at - inter + 1e-9f);
                            sup |= (iou > IOU_T);
                        }
                    }
                    unsigned wmask = __ballot_sync(0xFFFFFFFFu, sup);
                    if (lane == 0) s_presup[t >> 5] = wmask;
                }
            }

            // ---- suppression bit-matrix: row t marks u>t with IOU>T ----
            int W = (cnt + 31) >> 5;
            for (int t = tid; t < cnt; t += 256) {
                float4 Bt = cbox[t];
                float  at = carea[t];
                int wlo = (t + 1) >> 5;
                for (int w = wlo; w < W; ++w) {
                    unsigned word = 0;
                    int ub = w << 5;
                    int us = (ub > t + 1) ? ub : t + 1;
                    int ue = min(ub + 32, cnt);
                    for (int u = us; u < ue; ++u) {
                        float4 Bu = cbox[u];
                        float ix1 = fmaxf(Bt.x, Bu.x), iy1 = fmaxf(Bt.y, Bu.y);
                        float ix2 = fminf(Bt.z, Bu.z), iy2 = fminf(Bt.w, Bu.w);
                        float inter = fmaxf(ix2 - ix1, 0.0f) * fmaxf(iy2 - iy1, 0.0f);
                        float iou = inter / (at + carea[u] - inter + 1e-9f);
                        if (iou > IOU_T) word |= 1u << (u - ub);
                    }
                    s_mask[t * MAXW + w] = word;
                }
            }
            __syncthreads();

            // ---- single-thread scan, presup in REGISTERS ----
            if (tid == 0) {
                unsigned p0 = s_presup[0],  p1 = s_presup[1],  p2 = s_presup[2];
                unsigned p3 = s_presup[3],  p4 = s_presup[4],  p5 = s_presup[5];
                unsigned p6 = s_presup[6],  p7 = s_presup[7],  p8 = s_presup[8];
                unsigned p9 = s_presup[9],  p10 = s_presup[10], p11 = s_presup[11];
                int ns = s_ns;
                #define ORROW(T) { const unsigned* _r = &s_mask[(T) * MAXW]; \
                    p0 |= _r[0];  p1 |= _r[1];  p2 |= _r[2];  p3 |= _r[3]; \
                    p4 |= _r[4];  p5 |= _r[5];  p6 |= _r[6];  p7 |= _r[7]; \
                    p8 |= _r[8];  p9 |= _r[9];  p10 |= _r[10]; p11 |= _r[11]; }
                #define SCANW(WI, PW) \
                    if (ns < NMSMAX && (WI) * 32 < cnt) { \
                        int tend = min(cnt, ((WI) + 1) * 32); \
                        for (int t2 = (WI) * 32; t2 < tend; ++t2) { \
                            if (!((PW >> (t2 & 31)) & 1u)) { \
                                s_keep[ns++] = t2; \
                                ORROW(t2); \
                                if (ns >= NMSMAX) break; \
                            } \
                        } \
                    }
                SCANW(0, p0)  SCANW(1, p1)  SCANW(2, p2)  SCANW(3, p3)
                SCANW(4, p4)  SCANW(5, p5)  SCANW(6, p6)  SCANW(7, p7)
                SCANW(8, p8)  SCANW(9, p9)  SCANW(10, p10) SCANW(11, p11)
                #undef SCANW
                #undef ORROW
                s_ns = ns;
            }
            __syncthreads();

            // ---- parallel write of newly kept ----
            int nsNew = s_ns;
            for (int j = nsPrev + tid; j < nsNew; j += 256) {
                int t = s_keep[j];
                float4 Bt = cbox[t];
                int o = bc * NMSMAX + j;
                g_selscore[o] = funmap((unsigned)(cand[t] >> 32));
                g_selbox[o]   = Bt;
                kbox[j]  = Bt;
                karea[j] = carea[t];
            }
            __syncthreads();
        }

        if (s_ns >= NMSMAX) break;
        hiW = windowLo;
        if (hiW == 0) break;
    }

    for (int j = s_ns + tid; j < NMSMAX; j += 256)
        g_selscore[bc * NMSMAX + j] = -INFINITY;
}

// ---------------- phase 3: merge-count rank top-200 ------------------------
// keys per class are strictly descending. rank(key) = sum over all 20 classes
// of (# elements in that class greater than key); computed by 400 pair-merges
// split into 4 segments each, conflict-free uint8 count plane, then row sums.
__global__ void __launch_bounds__(512) topk_kernel(float* __restrict__ out)
{
    extern __shared__ char dyn[];
    unsigned long long* keys = (unsigned long long*)dyn;          // 2000 * 8 = 16000 B
    unsigned char*      cnt8 = (unsigned char*)(dyn + 16000);     // 2000 * 20 = 40000 B

    const int b   = blockIdx.x;
    const int tid = threadIdx.x;
    const int NK  = NCLS * NMSMAX;    // 2000

    for (int k = tid; k < NK; k += 512) {
        float s = g_selscore[b * NK + k];
        keys[k] = ((unsigned long long)fmap(s) << 32) |
                  (unsigned)(0xFFFFFFFFu - (unsigned)k);
    }
    __syncthreads();

    // 400 pairs * 4 segments of 25
    for (int u = tid; u < 400 * 4; u += 512) {
        int pair = u >> 2;
        int seg  = u & 3;
        int c0 = pair / NCLS;
        int cc = pair - c0 * NCLS;
        const unsigned long long* A = keys + c0 * NMSMAX;
        const unsigned long long* Bk = keys + cc * NMSMAX;
        int i0 = seg * 25;
        unsigned long long a = A[i0];
        // binary search: first j with Bk[j] <= a  (Bk strictly descending)
        int lo = 0, hi = NMSMAX;
        while (lo < hi) {
            int mid = (lo + hi) >> 1;
            if (Bk[mid] > a) lo = mid + 1; else hi = mid;
        }
        int jb = lo;
        cnt8[(c0 * NMSMAX + i0) * NCLS + cc] = (unsigned char)jb;
        for (int i = i0 + 1; i < i0 + 25; ++i) {
            a = A[i];
            while (jb < NMSMAX && Bk[jb] > a) ++jb;
            cnt8[(c0 * NMSMAX + i) * NCLS + cc] = (unsigned char)jb;
        }
    }
    __syncthreads();

    for (int k = tid; k < NK; k += 512) {
        int rank = 0;
        const unsigned char* row = cnt8 + k * NCLS;
        #pragma unroll
        for (int cc = 0; cc < NCLS; ++cc) rank += row[cc];
        if (rank < TOPK) {
            unsigned long long key = keys[k];
            unsigned hi = (unsigned)(key >> 32);
            float* o = out + ((size_t)b * TOPK + rank) * 6;
            if (hi != FM_NEGINF) {
                int c0 = k / NMSMAX;
                float4 box = g_selbox[b * NK + k];
                o[0] = (float)c0 + 1.0f;
                o[1] = funmap(hi);
                o[2] = box.x; o[3] = box.y; o[4] = box.z; o[5] = box.w;
            } else {
                o[0] = 1.0f; o[1] = 0.0f;
                o[2] = 0.0f; o[3] = 0.0f; o[4] = 0.0f; o[5] = 0.0f;
            }
        }
    }

    // reset candidate counters for the next replay
    if (tid < NCLS) g_candcnt[b * NCLS + tid] = 0;
}

// -----------------------------------------------------------------------------
extern "C" void kernel_launch(void* const* d_in, const int* in_sizes, int n_in,
                              void* d_out, int out_size)
{
    const float* y = (const float*)d_in[0];
    float* out = (float*)d_out;
    cudaFuncSetAttribute(topk_kernel, cudaFuncAttributeMaxDynamicSharedMemorySize, 56000);
    decode_kernel<<<BB * NTILES, 256>>>(y);
    nms_kernel<<<NBC, 256>>>(y);
    topk_kernel<<<BB, 512, 56000>>>(out);
}

// round 6
// speedup vs baseline: 1.1542x; 1.0921x over previous
#include <cuda_runtime.h>
#include <math.h>
#include <stdint.h>

#define BB     32
#define NN     8732
#define NCLS   20
#define DCOL   33
#define NMSMAX 100
#define TOPK   200
#define CONF_T 0.01f
#define IOU_T  0.45f
#define TILE   128
#define NTILES 69            // ceil(8732/128)
#define NBC    (BB * NCLS)   // 640
#define CAP    384
#define MAXW   12            // ceil(CAP/32)
#define NMS_T  128
#define TK_T   128

// ---------------- scratch ----------------
__device__ float4             g_boxes   [(size_t)BB * NN];
__device__ int                g_candcnt [NBC];            // zero-init; topk resets
__device__ unsigned long long g_cand    [NBC * CAP];
__device__ float              g_selscore[NBC * NMSMAX];
__device__ float4             g_selbox  [NBC * NMSMAX];

// monotonic float <-> u32 order-preserving map
__device__ __forceinline__ unsigned fmap(float f) {
    unsigned u = __float_as_uint(f);
    return (u & 0x80000000u) ? ~u : (u | 0x80000000u);
}
__device__ __forceinline__ float funmap(unsigned u) {
    return __uint_as_float((u & 0x80000000u) ? (u & 0x7FFFFFFFu) : ~u);
}
#define FM_NEGINF 0x007FFFFFu   // fmap(-inf)

__device__ __forceinline__ float4 decode_box_row(const float* __restrict__ r)
{
    float cx_p = r[21], cy_p = r[22], w_p = r[23], h_p = r[24];
    float xa1  = r[25], ya1  = r[26], xa2 = r[27], ya2 = r[28];
    float vcx  = r[29], vcy  = r[30], vw  = r[31], vh  = r[32];
    float w_a = xa2 - xa1, h_a = ya2 - ya1;
    float cx_a = (xa2 + xa1) * 0.5f, cy_a = (ya2 + ya1) * 0.5f;
    float cx = cx_p * vcx * w_a + cx_a;
    float cy = cy_p * vcy * h_a + cy_a;
    float w  = expf(w_p * vw) * w_a;
    float h  = expf(h_p * vh) * h_a;
    float4 o;
    o.x = (cx - 0.5f * w) * 512.0f;
    o.y = (cy - 0.5f * h) * 512.0f;
    o.z = (cx + 0.5f * w) * 512.0f;
    o.w = (cy + 0.5f * h) * 512.0f;
    return o;
}

// ---------------- phase 1: decode + candidate filter ----------------
__global__ void __launch_bounds__(256) decode_kernel(const float* __restrict__ y)
{
    __shared__ float sh[TILE * DCOL];
    const int tid = threadIdx.x;
    int blk = blockIdx.x;
    int b   = blk / NTILES;
    int t   = blk % NTILES;
    int n0  = t * TILE;
    int count = min(TILE, NN - n0);

    const float* src = y + ((size_t)b * NN + n0) * DCOL;
    for (int i = tid; i < count * DCOL; i += 256) sh[i] = src[i];
    __syncthreads();

    const unsigned LO = fmap(0.975f);
    if (count == TILE) {
        for (int k = tid; k < NCLS * TILE; k += 256) {
            int c  = k >> 7;
            int nn = k & (TILE - 1);
            float s = sh[nn * DCOL + 1 + c];
            if (s > CONF_T) {
                unsigned m = fmap(s);
                if (m >= LO) {
                    int bc = b * NCLS + c;
                    int q = atomicAdd(&g_candcnt[bc], 1);
                    if (q < CAP)
                        g_cand[bc * CAP + q] = ((unsigned long long)m << 32) |
                                               (unsigned)(0xFFFFFFFFu - (unsigned)(n0 + nn));
                }
            }
        }
    } else {
        for (int k = tid; k < NCLS * count; k += 256) {
            int c  = k / count;
            int nn = k - c * count;
            float s = sh[nn * DCOL + 1 + c];
            if (s > CONF_T) {
                unsigned m = fmap(s);
                if (m >= LO) {
                    int bc = b * NCLS + c;
                    int q = atomicAdd(&g_candcnt[bc], 1);
                    if (q < CAP)
                        g_cand[bc * CAP + q] = ((unsigned long long)m << 32) |
                                               (unsigned)(0xFFFFFFFFu - (unsigned)(n0 + nn));
                }
            }
        }
    }
    if (tid < count)
        g_boxes[(size_t)b * NN + n0 + tid] = decode_box_row(sh + tid * DCOL);
}

// ---------------- phase 2: bitmask NMS, 128 threads per (b,c) ---------------
__global__ void __launch_bounds__(NMS_T) nms_kernel(const float* __restrict__ y)
{
    const int bc = blockIdx.x;
    const int b  = bc / NCLS;
    const int c  = bc - b * NCLS;
    const float4* bx = g_boxes + (size_t)b * NN;

    __shared__ unsigned long long cand[512];      // 4 KB
    __shared__ float4   cbox [CAP];               // 6 KB
    __shared__ float    carea[CAP];               // 1.5 KB
    __shared__ unsigned s_mask[CAP * MAXW];       // 18 KB
    __shared__ float4   kbox [NMSMAX];
    __shared__ float    karea[NMSMAX];
    __shared__ unsigned s_presup[MAXW];
    __shared__ int      s_keep[NMSMAX];
    __shared__ int      s_cnt, s_ns;

    const int tid  = threadIdx.x;
    const int lane = tid & 31;
    const unsigned LO = fmap(0.975f);
    if (tid == 0) s_ns = 0;

    int cnt0 = g_candcnt[bc];
    bool listFirst = (cnt0 <= CAP);
    unsigned hiW = listFirst ? LO : 0xFFFFFFFFu;
    __syncthreads();

    for (;;) {
        int cnt;
        unsigned windowLo;

        if (listFirst) {
            listFirst = false;
            cnt = cnt0;
            for (int i = tid; i < cnt; i += NMS_T) cand[i] = g_cand[bc * CAP + i];
            windowLo = hiW;
            __syncthreads();
        } else {
            // exact fallback: gather from raw y in [loW, hiW), halving on overflow
            unsigned loW = 0;
            for (;;) {
                __syncthreads();
                if (tid == 0) s_cnt = 0;
                __syncthreads();
                for (int i = tid; i < NN; i += NMS_T) {
                    float val = y[((size_t)b * NN + i) * DCOL + 1 + c];
                    if (val > CONF_T) {
                        unsigned m = fmap(val);
                        if (m >= loW && m < hiW) {
                            int p = atomicAdd(&s_cnt, 1);
                            if (p < CAP)
                                cand[p] = ((unsigned long long)m << 32) |
                                          (unsigned)(0xFFFFFFFFu - (unsigned)i);
                        }
                    }
                }
                __syncthreads();
                cnt = s_cnt;
                if (cnt <= CAP || hiW - loW <= 1) break;
                loW = loW + ((hiW - loW) >> 1);
            }
            if (cnt > CAP) cnt = CAP;
            windowLo = loW;
        }

        if (cnt > 0) {
            // ---- bitonic sort descending ----
            int P = 32; while (P < cnt) P <<= 1;
            for (int i = cnt + tid; i < P; i += NMS_T) cand[i] = 0ull;
            __syncthreads();
            for (int ks = 2; ks <= P; ks <<= 1) {
                for (int j = ks >> 1; j > 0; j >>= 1) {
                    for (int i = tid; i < P; i += NMS_T) {
                        int ixj = i ^ j;
                        if (ixj > i) {
                            unsigned long long a = cand[i], q = cand[ixj];
                            bool desc = ((i & ks) == 0);
                            if (desc ? (a < q) : (a > q)) { cand[i] = q; cand[ixj] = a; }
                        }
                    }
                    __syncthreads();
                }
            }

            // ---- boxes + areas in sorted order ----
            for (int t = tid; t < cnt; t += NMS_T) {
                int idx = (int)(0xFFFFFFFFu - (unsigned)(cand[t] & 0xFFFFFFFFull));
                float4 Bt = __ldg(&bx[idx]);
                cbox[t]  = Bt;
                carea[t] = fmaxf(Bt.z - Bt.x, 0.0f) * fmaxf(Bt.w - Bt.y, 0.0f);
            }
            if (tid < MAXW) s_presup[tid] = 0;
            __syncthreads();

            // ---- pre-suppression vs kept boxes of earlier windows ----
            int nsPrev = s_ns;
            if (nsPrev > 0) {
                int P32 = (cnt + 31) & ~31;
                for (int t = tid; t < P32; t += NMS_T) {
                    bool sup = false;
                    if (t < cnt) {
                        float4 Bt = cbox[t];
                        float at = carea[t];
                        for (int j = 0; j < nsPrev; ++j) {
                            float4 Kj = kbox[j];
                            float ix1 = fmaxf(Kj.x, Bt.x), iy1 = fmaxf(Kj.y, Bt.y);
                            float ix2 = fminf(Kj.z, Bt.z), iy2 = fminf(Kj.w, Bt.w);
                            float inter = fmaxf(ix2 - ix1, 0.0f) * fmaxf(iy2 - iy1, 0.0f);
                            float iou = inter / (karea[j] + at - inter + 1e-9f);
                            sup |= (iou > IOU_T);
                        }
                    }
                    unsigned wmask = __ballot_sync(0xFFFFFFFFu, sup);
                    if (lane == 0) s_presup[t >> 5] = wmask;
                }
            }

            // ---- suppression bit-matrix: row t marks u>t with IOU>T ----
            int W = (cnt + 31) >> 5;
            for (int t = tid; t < cnt; t += NMS_T) {
                float4 Bt = cbox[t];
                float  at = carea[t];
                int wlo = (t + 1) >> 5;
                for (int w = wlo; w < W; ++w) {
                    unsigned word = 0;
                    int ub = w << 5;
                    int us = (ub > t + 1) ? ub : t + 1;
                    int ue = min(ub + 32, cnt);
                    for (int u = us; u < ue; ++u) {
                        float4 Bu = cbox[u];
                        float ix1 = fmaxf(Bt.x, Bu.x), iy1 = fmaxf(Bt.y, Bu.y);
                        float ix2 = fminf(Bt.z, Bu.z), iy2 = fminf(Bt.w, Bu.w);
                        float inter = fmaxf(ix2 - ix1, 0.0f) * fmaxf(iy2 - iy1, 0.0f);
                        float iou = inter / (at + carea[u] - inter + 1e-9f);
                        if (iou > IOU_T) word |= 1u << (u - ub);
                    }
                    s_mask[t * MAXW + w] = word;
                }
            }
            __syncthreads();

            // ---- single-thread scan, presup in registers ----
            if (tid == 0) {
                unsigned p0 = s_presup[0],  p1 = s_presup[1],  p2 = s_presup[2];
                unsigned p3 = s_presup[3],  p4 = s_presup[4],  p5 = s_presup[5];
                unsigned p6 = s_presup[6],  p7 = s_presup[7],  p8 = s_presup[8];
                unsigned p9 = s_presup[9],  p10 = s_presup[10], p11 = s_presup[11];
                int ns = s_ns;
                #define ORROW(T) { const unsigned* _r = &s_mask[(T) * MAXW]; \
                    p0 |= _r[0];  p1 |= _r[1];  p2 |= _r[2];  p3 |= _r[3]; \
                    p4 |= _r[4];  p5 |= _r[5];  p6 |= _r[6];  p7 |= _r[7]; \
                    p8 |= _r[8];  p9 |= _r[9];  p10 |= _r[10]; p11 |= _r[11]; }
                #define SCANW(WI, PW) \
                    if (ns < NMSMAX && (WI) * 32 < cnt) { \
                        int tend = min(cnt, ((WI) + 1) * 32); \
                        for (int t2 = (WI) * 32; t2 < tend; ++t2) { \
                            if (!((PW >> (t2 & 31)) & 1u)) { \
                                s_keep[ns++] = t2; \
                                ORROW(t2); \
                                if (ns >= NMSMAX) break; \
                            } \
                        } \
                    }
                SCANW(0, p0)  SCANW(1, p1)  SCANW(2, p2)  SCANW(3, p3)
                SCANW(4, p4)  SCANW(5, p5)  SCANW(6, p6)  SCANW(7, p7)
                SCANW(8, p8)  SCANW(9, p9)  SCANW(10, p10) SCANW(11, p11)
                #undef SCANW
                #undef ORROW
                s_ns = ns;
            }
            __syncthreads();

            // ---- parallel write of newly kept ----
            int nsNew = s_ns;
            for (int j = nsPrev + tid; j < nsNew; j += NMS_T) {
                int t = s_keep[j];
                float4 Bt = cbox[t];
                int o = bc * NMSMAX + j;
                g_selscore[o] = funmap((unsigned)(cand[t] >> 32));
                g_selbox[o]   = Bt;
                kbox[j]  = Bt;
                karea[j] = carea[t];
            }
            __syncthreads();
        }

        if (s_ns >= NMSMAX) break;
        hiW = windowLo;
        if (hiW == 0) break;
    }

    for (int j = s_ns + tid; j < NMSMAX; j += NMS_T)
        g_selscore[bc * NMSMAX + j] = -INFINITY;
}

// ---------------- phase 3: rank-scatter top-200, one CTA per (b,c0) --------
// Per-class key lists are strictly descending. Global rank of a key =
// own-list position + sum over other 19 lists of (# keys greater).
// All 2000 keys of a batch have distinct ranks 0..1999; rows with rank<200
// are scattered directly to out. Exactly matches lax.top_k ordering.
__global__ void __launch_bounds__(TK_T) topk_kernel(float* __restrict__ out)
{
    const int bc  = blockIdx.x;
    const int b   = bc / NCLS;
    const int c0  = bc - b * NCLS;
    const int tid = threadIdx.x;
    const int NK  = NCLS * NMSMAX;   // 2000

    __shared__ unsigned long long keys[NK];   // 16 KB
    __shared__ int s_rank[NMSMAX];

    for (int k = tid; k < NK; k += TK_T) {
        float s = g_selscore[b * NK + k];
        keys[k] = ((unsigned long long)fmap(s) << 32) |
                  (unsigned)(0xFFFFFFFFu - (unsigned)k);
    }
    if (tid < NMSMAX) s_rank[tid] = tid;      // own-list position (desc list)
    __syncthreads();

    // 100 own keys x 19 other lists = 1900 binary-search units
    for (int u = tid; u < NMSMAX * (NCLS - 1); u += TK_T) {
        int i = u / (NCLS - 1);
        int j = u - i * (NCLS - 1);
        int cc = j + (j >= c0);
        unsigned long long my = keys[c0 * NMSMAX + i];
        const unsigned long long* L = keys + cc * NMSMAX;
        int lo = 0, hi = NMSMAX;
        while (lo < hi) {
            int mid = (lo + hi) >> 1;
            if (L[mid] > my) lo = mid + 1; else hi = mid;
        }
        atomicAdd(&s_rank[i], lo);
    }
    __syncthreads();

    if (tid < NMSMAX) {
        int r = s_rank[tid];
        if (r < TOPK) {
            unsigned long long key = keys[c0 * NMSMAX + tid];
            unsigned hi = (unsigned)(key >> 32);
            float* o = out + ((size_t)b * TOPK + r) * 6;
            if (hi != FM_NEGINF) {
                float4 box = g_selbox[bc * NMSMAX + tid];
                o[0] = (float)c0 + 1.0f;
                o[1] = funmap(hi);
                o[2] = box.x; o[3] = box.y; o[4] = box.z; o[5] = box.w;
            } else {
                o[0] = 1.0f; o[1] = 0.0f;
                o[2] = 0.0f; o[3] = 0.0f; o[4] = 0.0f; o[5] = 0.0f;
            }
        }
    }

    if (tid == 0) g_candcnt[bc] = 0;   // reset for next replay
}

// -----------------------------------------------------------------------------
extern "C" void kernel_launch(void* const* d_in, const int* in_sizes, int n_in,
                              void* d_out, int out_size)
{
    const float* y = (const float*)d_in[0];
    float* out = (float*)d_out;
    decode_kernel<<<BB * NTILES, 256>>>(y);
    nms_kernel<<<NBC, NMS_T>>>(y);
    topk_kernel<<<NBC, TK_T>>>(out);
}